// round 1
// baseline (speedup 1.0000x reference)
#include <cuda_runtime.h>
#include <math.h>

// Problem constants (fixed shapes from reference)
#define T_TOK 1024
#define H_DIM 2048
#define I_DIM 1408
#define E_NUM 8

// ---------------- device scratch (no runtime allocation allowed) ----------------
__device__ int   g_count[E_NUM];
__device__ int   g_tok[E_NUM * T_TOK];
__device__ float g_wt [E_NUM * T_TOK];
// routed h = silu(g)*u, laid out per-expert with fixed stride T_TOK rows
__device__ float g_hroute[(size_t)E_NUM * T_TOK * I_DIM];   // ~46 MB
__device__ float g_hshared[(size_t)T_TOK * I_DIM];          // ~5.8 MB

// ---------------- zero kernel ----------------
__global__ void zero_kernel(float* __restrict__ out, int n) {
    int i = blockIdx.x * blockDim.x + threadIdx.x;
    if (i < n) out[i] = 0.0f;
    if (i < E_NUM) g_count[i] = 0;
}

// ---------------- routing: logits -> top2 -> softmax -> scatter ----------------
__global__ void routing_kernel(const float* __restrict__ x,
                               const float* __restrict__ gw) {
    int t = blockIdx.x * blockDim.x + threadIdx.x;
    if (t >= T_TOK) return;
    float logits[E_NUM];
#pragma unroll
    for (int e = 0; e < E_NUM; e++) logits[e] = 0.0f;
    const float* xr = x + (size_t)t * H_DIM;
    for (int h = 0; h < H_DIM; h += 4) {
        float4 xv = *(const float4*)(xr + h);
#pragma unroll
        for (int e = 0; e < E_NUM; e++) {
            const float* wr = gw + (size_t)e * H_DIM + h;
            logits[e] += xv.x * wr[0] + xv.y * wr[1] + xv.z * wr[2] + xv.w * wr[3];
        }
    }
    // top-2 (first occurrence wins on ties, matching top_k semantics)
    int i0 = 0;
#pragma unroll
    for (int e = 1; e < E_NUM; e++) if (logits[e] > logits[i0]) i0 = e;
    int i1 = -1;
#pragma unroll
    for (int e = 0; e < E_NUM; e++) {
        if (e == i0) continue;
        if (i1 < 0 || logits[e] > logits[i1]) i1 = e;
    }
    float l0 = logits[i0], l1 = logits[i1];
    float e1 = expf(l1 - l0);
    float inv = 1.0f / (1.0f + e1);
    float w0 = inv;            // softmax of (l0, l1)
    float w1 = e1 * inv;

    int s0 = atomicAdd(&g_count[i0], 1);
    g_tok[i0 * T_TOK + s0] = t;
    g_wt [i0 * T_TOK + s0] = w0;
    int s1 = atomicAdd(&g_count[i1], 1);
    g_tok[i1 * T_TOK + s1] = t;
    g_wt [i1 * T_TOK + s1] = w1;
}

// ---------------- fused gate+up GEMM with silu epilogue ----------------
// C[m][n] = sum_k A[m][k] * W[n][k]  (A gathered token rows, W is [I,H] row-major)
// 64x64 tile, BK=16, 256 threads, 4x4 microtile, dual accumulators (gate & up).
__global__ void gateup_kernel(const float* __restrict__ X,
                              const float* __restrict__ Wg,
                              const float* __restrict__ Wu,
                              float* __restrict__ Hout,
                              int routed) {
    __shared__ float As[16][65];
    __shared__ float Bg[16][65];
    __shared__ float Bu[16][65];

    int e = blockIdx.z;
    int count = routed ? g_count[e] : T_TOK;
    int m0 = blockIdx.y * 64;
    if (m0 >= count) return;
    int n0 = blockIdx.x * 64;

    const float* wgB = Wg + (size_t)e * I_DIM * H_DIM;
    const float* wuB = Wu + (size_t)e * I_DIM * H_DIM;

    int tid = threadIdx.x;
    int lr = tid >> 2;          // 0..63 : row within tile for loading
    int lc = (tid & 3) * 4;     // 0,4,8,12 : float4 column group

    int arow = m0 + lr;
    const float* aptr = nullptr;
    if (arow < count) {
        int t = routed ? g_tok[e * T_TOK + arow] : arow;
        aptr = X + (size_t)t * H_DIM;
    }
    const float* bgp = wgB + (size_t)(n0 + lr) * H_DIM;
    const float* bup = wuB + (size_t)(n0 + lr) * H_DIM;

    int tx = tid & 15, ty = tid >> 4;
    float accg[4][4] = {}, accu[4][4] = {};

    for (int k0 = 0; k0 < H_DIM; k0 += 16) {
        float4 av = make_float4(0.f, 0.f, 0.f, 0.f);
        if (aptr) av = *(const float4*)(aptr + k0 + lc);
        float4 gv = *(const float4*)(bgp + k0 + lc);
        float4 uv = *(const float4*)(bup + k0 + lc);
        As[lc + 0][lr] = av.x; As[lc + 1][lr] = av.y;
        As[lc + 2][lr] = av.z; As[lc + 3][lr] = av.w;
        Bg[lc + 0][lr] = gv.x; Bg[lc + 1][lr] = gv.y;
        Bg[lc + 2][lr] = gv.z; Bg[lc + 3][lr] = gv.w;
        Bu[lc + 0][lr] = uv.x; Bu[lc + 1][lr] = uv.y;
        Bu[lc + 2][lr] = uv.z; Bu[lc + 3][lr] = uv.w;
        __syncthreads();
#pragma unroll
        for (int kk = 0; kk < 16; kk++) {
            float a[4], b0[4], b1[4];
#pragma unroll
            for (int i = 0; i < 4; i++) a[i] = As[kk][ty * 4 + i];
#pragma unroll
            for (int j = 0; j < 4; j++) { b0[j] = Bg[kk][tx * 4 + j]; b1[j] = Bu[kk][tx * 4 + j]; }
#pragma unroll
            for (int i = 0; i < 4; i++)
#pragma unroll
                for (int j = 0; j < 4; j++) {
                    accg[i][j] += a[i] * b0[j];
                    accu[i][j] += a[i] * b1[j];
                }
        }
        __syncthreads();
    }

    size_t rowbase = routed ? (size_t)e * T_TOK : 0;
#pragma unroll
    for (int i = 0; i < 4; i++) {
        int m = m0 + ty * 4 + i;
        if (m >= count) continue;
        size_t ro = (rowbase + m) * (size_t)I_DIM + n0 + tx * 4;
#pragma unroll
        for (int j = 0; j < 4; j++) {
            float g = accg[i][j];
            float u = accu[i][j];
            float s = g / (1.0f + __expf(-g));   // silu
            Hout[ro + j] = s * u;
        }
    }
}

// ---------------- down GEMM with weighted atomic scatter ----------------
// out[t][n] += wt * sum_i H[m][i] * Wd[n][i]   (Wd is [H,I] row-major)
__global__ void down_kernel(const float* __restrict__ Hbuf,
                            const float* __restrict__ Wd,
                            float* __restrict__ out,
                            int routed) {
    __shared__ float As[16][65];
    __shared__ float Bs[16][65];

    int e = blockIdx.z;
    int count = routed ? g_count[e] : T_TOK;
    int m0 = blockIdx.y * 64;
    if (m0 >= count) return;
    int n0 = blockIdx.x * 64;

    const float* wdB = Wd + (size_t)e * H_DIM * I_DIM;

    int tid = threadIdx.x;
    int lr = tid >> 2;
    int lc = (tid & 3) * 4;

    int arow = m0 + lr;
    const float* aptr = nullptr;
    if (arow < count) {
        size_t rowbase = routed ? (size_t)e * T_TOK : 0;
        aptr = Hbuf + (rowbase + arow) * (size_t)I_DIM;
    }
    const float* bp = wdB + (size_t)(n0 + lr) * I_DIM;

    int tx = tid & 15, ty = tid >> 4;
    float acc[4][4] = {};

    for (int k0 = 0; k0 < I_DIM; k0 += 16) {
        float4 av = make_float4(0.f, 0.f, 0.f, 0.f);
        if (aptr) av = *(const float4*)(aptr + k0 + lc);
        float4 bv = *(const float4*)(bp + k0 + lc);
        As[lc + 0][lr] = av.x; As[lc + 1][lr] = av.y;
        As[lc + 2][lr] = av.z; As[lc + 3][lr] = av.w;
        Bs[lc + 0][lr] = bv.x; Bs[lc + 1][lr] = bv.y;
        Bs[lc + 2][lr] = bv.z; Bs[lc + 3][lr] = bv.w;
        __syncthreads();
#pragma unroll
        for (int kk = 0; kk < 16; kk++) {
            float a[4], b[4];
#pragma unroll
            for (int i = 0; i < 4; i++) a[i] = As[kk][ty * 4 + i];
#pragma unroll
            for (int j = 0; j < 4; j++) b[j] = Bs[kk][tx * 4 + j];
#pragma unroll
            for (int i = 0; i < 4; i++)
#pragma unroll
                for (int j = 0; j < 4; j++) acc[i][j] += a[i] * b[j];
        }
        __syncthreads();
    }

#pragma unroll
    for (int i = 0; i < 4; i++) {
        int m = m0 + ty * 4 + i;
        if (m >= count) continue;
        int t;
        float wt;
        if (routed) {
            t  = g_tok[e * T_TOK + m];
            wt = g_wt [e * T_TOK + m];
        } else {
            t = m; wt = 1.0f;
        }
        float* orow = out + (size_t)t * H_DIM + n0 + tx * 4;
#pragma unroll
        for (int j = 0; j < 4; j++) atomicAdd(&orow[j], wt * acc[i][j]);
    }
}

// ---------------- launch ----------------
extern "C" void kernel_launch(void* const* d_in, const int* in_sizes, int n_in,
                              void* d_out, int out_size) {
    const float* x   = (const float*)d_in[0];   // [1,1024,2048]
    const float* gw  = (const float*)d_in[1];   // [8,2048]
    const float* egw = (const float*)d_in[2];   // [8,1408,2048]
    const float* euw = (const float*)d_in[3];   // [8,1408,2048]
    const float* edw = (const float*)d_in[4];   // [8,2048,1408]
    const float* sgw = (const float*)d_in[5];   // [1408,2048]
    const float* suw = (const float*)d_in[6];   // [1408,2048]
    const float* sdw = (const float*)d_in[7];   // [2048,1408]
    float* out = (float*)d_out;                 // [1,1024,2048]

    int n_out = T_TOK * H_DIM;
    zero_kernel<<<(n_out + 255) / 256, 256>>>(out, n_out);
    routing_kernel<<<T_TOK / 256, 256>>>(x, gw);

    // routed experts
    {
        dim3 grid(I_DIM / 64, T_TOK / 64, E_NUM);
        gateup_kernel<<<grid, 256>>>(x, egw, euw, g_hroute, 1);
    }
    {
        dim3 grid(H_DIM / 64, T_TOK / 64, E_NUM);
        down_kernel<<<grid, 256>>>(g_hroute, edw, out, 1);
    }
    // shared expert
    {
        dim3 grid(I_DIM / 64, T_TOK / 64, 1);
        gateup_kernel<<<grid, 256>>>(x, sgw, suw, g_hshared, 0);
    }
    {
        dim3 grid(H_DIM / 64, T_TOK / 64, 1);
        down_kernel<<<grid, 256>>>(g_hshared, sdw, out, 0);
    }
}